// round 11
// baseline (speedup 1.0000x reference)
#include <cuda_runtime.h>
#include <cuda_bf16.h>
#include <cstdint>

// Problem constants
#define Lq   2048
#define Bb   4
#define Ee   1024
#define Hh   16
#define HD   64
#define BHh  64            // Bb*Hh
#define Mrows (Lq*Bb)      // 8192
#define SEG  ((size_t)BHh * Lq * HD)     // 8388608
#define ME   ((size_t)Mrows * Ee)        // 8388608
#define EE   ((size_t)Ee * Ee)           // 1048576

// bf16 split operands
__device__ __nv_bfloat16 g_xh[3 * ME], g_xl[3 * ME];       // q,k,v activations (prep)
__device__ __nv_bfloat16 g_wh[4 * EE], g_wl[4 * EE];       // in_proj_weight (3EE) + out_w (EE)
__device__ __nv_bfloat16 g_qkvh[3 * SEG], g_qkvl[3 * SEG]; // projected Q,K,V (BH,L,HD)
__device__ __nv_bfloat16 g_oh[SEG], g_ol[SEG];             // attention output

typedef unsigned long long u64;

// ---------------------------------------------------------------------------
// helpers
// ---------------------------------------------------------------------------
__device__ __forceinline__ uint32_t smem_u32(const void* p) {
    uint32_t a;
    asm("{ .reg .u64 t; cvta.to.shared.u64 t, %1; cvt.u32.u64 %0, t; }"
        : "=r"(a) : "l"(p));
    return a;
}
#define CP16(dst, src) asm volatile("cp.async.cg.shared.global [%0], [%1], 16;" :: "r"(dst), "l"(src))
#define CP_COMMIT()    asm volatile("cp.async.commit_group;" ::: "memory")
#define CP_WAIT(n)     asm volatile("cp.async.wait_group %0;" :: "n"(n) : "memory")

__device__ __forceinline__ void mma_bf16(float* c, const uint32_t* a, const uint32_t* b) {
    asm volatile(
        "mma.sync.aligned.m16n8k16.row.col.f32.bf16.bf16.f32 "
        "{%0,%1,%2,%3}, {%4,%5,%6,%7}, {%8,%9}, {%0,%1,%2,%3};"
        : "+f"(c[0]), "+f"(c[1]), "+f"(c[2]), "+f"(c[3])
        : "r"(a[0]), "r"(a[1]), "r"(a[2]), "r"(a[3]), "r"(b[0]), "r"(b[1]));
}
__device__ __forceinline__ void ldsm_x4(uint32_t* r, uint32_t a) {
    asm volatile("ldmatrix.sync.aligned.m8n8.x4.shared.b16 {%0,%1,%2,%3}, [%4];"
        : "=r"(r[0]), "=r"(r[1]), "=r"(r[2]), "=r"(r[3]) : "r"(a));
}
__device__ __forceinline__ void ldsm_x2(uint32_t* r, uint32_t a) {
    asm volatile("ldmatrix.sync.aligned.m8n8.x2.shared.b16 {%0,%1}, [%2];"
        : "=r"(r[0]), "=r"(r[1]) : "r"(a));
}
__device__ __forceinline__ void ldsm_x2t(uint32_t* r, uint32_t a) {
    asm volatile("ldmatrix.sync.aligned.m8n8.x2.trans.shared.b16 {%0,%1}, [%2];"
        : "=r"(r[0]), "=r"(r[1]) : "r"(a));
}

__device__ __forceinline__ void split_bf(float x, unsigned short& h, unsigned short& l) {
    h = __bfloat16_as_ushort(__float2bfloat16(x));
    float r = x - __bfloat162float(__ushort_as_bfloat16(h));
    l = __bfloat16_as_ushort(__float2bfloat16(r));
}
__device__ __forceinline__ void split_pack2(float f0, float f1, uint32_t& hi, uint32_t& lo) {
    unsigned short h0, h1, l0, l1;
    split_bf(f0, h0, l0); split_bf(f1, h1, l1);
    hi = (uint32_t)h0 | ((uint32_t)h1 << 16);
    lo = (uint32_t)l0 | ((uint32_t)l1 << 16);
}

// ---------------------------------------------------------------------------
// prep: split activations + weights into bf16 hi/lo. One float4 per thread.
// ---------------------------------------------------------------------------
#define NX4 ((3 * ME + 4 * EE) / 4)
__global__ __launch_bounds__(256)
void prep_kernel(const float* __restrict__ q, const float* __restrict__ k,
                 const float* __restrict__ v, const float* __restrict__ w,
                 const float* __restrict__ ow)
{
    size_t i4 = (size_t)blockIdx.x * 256 + threadIdx.x;
    if (i4 >= NX4) return;
    size_t base = i4 * 4;
    const float* src;
    __nv_bfloat16 *dh, *dl;
    if (base < 3 * ME) {
        size_t z = base / ME, off = base - z * ME;
        src = (z == 0 ? q : z == 1 ? k : v) + off;
        dh = g_xh + base; dl = g_xl + base;
    } else {
        size_t off = base - 3 * ME;
        src = (off < 3 * EE) ? (w + off) : (ow + (off - 3 * EE));
        dh = g_wh + off; dl = g_wl + off;
    }
    float4 f = *(const float4*)src;
    uint32_t h0, l0, h1, l1;
    split_pack2(f.x, f.y, h0, l0);
    split_pack2(f.z, f.w, h1, l1);
    *(uint2*)dh = make_uint2(h0, h1);
    *(uint2*)dl = make_uint2(l0, l1);
}

// ---------------------------------------------------------------------------
// GEMM on mma.sync bf16x3 + ldmatrix. CTA 128x128, K-iter 64, 2-stage cp.async.
// MODE 0: QKV projection (writes bf16 hi/lo Q,K,V), MODE 1: out projection.
// ---------------------------------------------------------------------------
#define TP    (128 * 144)
#define STG   (4 * TP)
#define SMEM_T (2 * STG)
#define NIT   16

template<int MODE>
__global__ __launch_bounds__(256)
void gemm_tc(const float* __restrict__ bias, float* __restrict__ outp)
{
    extern __shared__ __align__(128) char smem[];
    const uint32_t sbase = smem_u32(smem);

    const int z   = (MODE == 0) ? blockIdx.z : 0;
    const int bm  = blockIdx.y * 128;
    const int bn  = blockIdx.x * 128;
    const int tid = threadIdx.x;
    const int wid  = tid >> 5;
    const int lane = tid & 31;
    const int wm = wid & 3;
    const int wn = wid >> 2;

    const int r    = tid >> 1;
    const int half = tid & 1;

    const __nv_bfloat16 *a_h, *a_l;
    if (MODE == 0) {
        size_t arow = (size_t)z * ME + (size_t)(bm + r) * Ee + half * 32;
        a_h = g_xh + arow; a_l = g_xl + arow;
    } else {
        const int mrow = bm + r;
        const int lA = mrow >> 2, bA = mrow & 3;
        size_t arow = ((size_t)bA * Hh * Lq + lA) * HD + half * 32;
        a_h = g_oh + arow; a_l = g_ol + arow;
    }
    const size_t brow = (size_t)((MODE == 0 ? z * Ee : 3 * Ee) + bn + r) * Ee + half * 32;
    const __nv_bfloat16* b_h = g_wh + brow;
    const __nv_bfloat16* b_l = g_wl + brow;

    const size_t a_step = (MODE == 0) ? 64 : (size_t)Lq * HD;
    const size_t b_step = 64;

    const uint32_t dst_r = sbase + r * 144 + half * 64;

    // ldmatrix per-lane offsets
    const uint32_t a_lo = (uint32_t)((lane & 15) * 144 + (lane >> 4) * 16);
    const uint32_t b_lo = (uint32_t)((lane & 7) * 144 + ((lane >> 3) & 1) * 16);

    float acc[2][8][4];
#pragma unroll
    for (int i = 0; i < 2; i++)
#pragma unroll
        for (int j = 0; j < 8; j++)
#pragma unroll
            for (int t = 0; t < 4; t++) acc[i][j][t] = 0.0f;

    auto load_stage = [&](int it, int s) {
        const uint32_t d = dst_r + s * STG;
        const __nv_bfloat16* pa_h = a_h + (size_t)it * a_step;
        const __nv_bfloat16* pa_l = a_l + (size_t)it * a_step;
        const __nv_bfloat16* pb_h = b_h + (size_t)it * b_step;
        const __nv_bfloat16* pb_l = b_l + (size_t)it * b_step;
#pragma unroll
        for (int c = 0; c < 4; c++) {
            CP16(d + 0 * TP + c * 16, pa_h + c * 8);
            CP16(d + 1 * TP + c * 16, pa_l + c * 8);
            CP16(d + 2 * TP + c * 16, pb_h + c * 8);
            CP16(d + 3 * TP + c * 16, pb_l + c * 8);
        }
    };

    const int g  = lane >> 2;
    const int tc = lane & 3;

    load_stage(0, 0); CP_COMMIT();

    for (int it = 0; it < NIT; it++) {
        if (it + 1 < NIT) { load_stage(it + 1, (it + 1) & 1); CP_COMMIT(); CP_WAIT(1); }
        else              { CP_WAIT(0); }
        __syncthreads();

        const uint32_t st = sbase + (it & 1) * STG;
        const uint32_t a_base = st + (uint32_t)(wm * 32) * 144 + a_lo;
        const uint32_t b_base = st + 2 * TP + (uint32_t)(wn * 64) * 144 + b_lo;

#pragma unroll
        for (int ks = 0; ks < 4; ks++) {
            uint32_t ah[2][4], al[2][4];
            ldsm_x4(ah[0], a_base + ks * 32);
            ldsm_x4(ah[1], a_base + 16 * 144 + ks * 32);
            ldsm_x4(al[0], a_base + TP + ks * 32);
            ldsm_x4(al[1], a_base + TP + 16 * 144 + ks * 32);
#pragma unroll
            for (int nt = 0; nt < 8; nt++) {
                uint32_t bh[2], bl[2];
                ldsm_x2(bh, b_base + nt * 8 * 144 + ks * 32);
                ldsm_x2(bl, b_base + TP + nt * 8 * 144 + ks * 32);
#pragma unroll
                for (int mt = 0; mt < 2; mt++) {
                    mma_bf16(acc[mt][nt], ah[mt], bh);
                    mma_bf16(acc[mt][nt], ah[mt], bl);
                    mma_bf16(acc[mt][nt], al[mt], bh);
                }
            }
        }
        __syncthreads();
    }

    const float scale = (MODE == 0 && z == 0) ? 0.125f : 1.0f;
#pragma unroll
    for (int mt = 0; mt < 2; mt++) {
#pragma unroll
        for (int half_m = 0; half_m < 2; half_m++) {
            const int m = bm + wm * 32 + mt * 16 + g + half_m * 8;
#pragma unroll
            for (int nt = 0; nt < 8; nt++) {
                const int n = bn + wn * 64 + nt * 8 + tc * 2;
                const float c0 = acc[mt][nt][half_m * 2 + 0];
                const float c1 = acc[mt][nt][half_m * 2 + 1];
                if (MODE == 0) {
                    const int l = m >> 2, b = m & 3;
                    const int h = n >> 6, d = n & 63;
                    float v0 = scale * (c0 + bias[z * Ee + n]);
                    float v1 = scale * (c1 + bias[z * Ee + n + 1]);
                    uint32_t hi, lo;
                    split_pack2(v0, v1, hi, lo);
                    size_t addr = (size_t)z * SEG + ((size_t)(b * Hh + h) * Lq + l) * HD + d;
                    *(uint32_t*)&g_qkvh[addr] = hi;
                    *(uint32_t*)&g_qkvl[addr] = lo;
                } else {
                    float2 t;
                    t.x = c0 + bias[n];
                    t.y = c1 + bias[n + 1];
                    *(float2*)&outp[(size_t)m * Ee + n] = t;
                }
            }
        }
    }
}

// ---------------------------------------------------------------------------
// Flash attention on mma.sync bf16x3 + ldmatrix, 2-stage cp.async K/V pipe.
// CTA = (head, 128 q rows), 8 warps x 16 rows. K-tile = 128 tokens.
// K and V both token-major in smem (144B rows).
// QK B-frags: ldmatrix.x2; PV B-frags: ldmatrix.x2.trans (no V transpose!).
// ---------------------------------------------------------------------------
#define AT_KH   0
#define AT_KL   (128 * 144)
#define AT_VH   (2 * 128 * 144)
#define AT_VL   (3 * 128 * 144)
#define AT_STG  (4 * 128 * 144)          // 73728 per stage
#define SM_ATTN (2 * AT_STG)             // 147456

__global__ __launch_bounds__(256)
void attn_mma()
{
    extern __shared__ __align__(128) char smem[];
    const uint32_t sb = smem_u32(smem);

    const int head = blockIdx.y;
    const int q0   = blockIdx.x * 128;
    const int tid  = threadIdx.x;
    const int wid  = tid >> 5;
    const int lane = tid & 31;
    const int g    = lane >> 2;
    const int tc   = lane & 3;

    const __nv_bfloat16* Qh = g_qkvh;
    const __nv_bfloat16* Ql = g_qkvl;
    const __nv_bfloat16* Kh = g_qkvh + SEG;
    const __nv_bfloat16* Kl = g_qkvl + SEG;
    const __nv_bfloat16* Vh = g_qkvh + 2 * SEG;
    const __nv_bfloat16* Vl = g_qkvl + 2 * SEG;

    // Q fragments in registers (per warp: 16 rows x 64 hd)
    uint32_t qa_h[4][4], qa_l[4][4];
    {
        const size_t r0 = (size_t)head * Lq + q0 + wid * 16 + g;
        const size_t r1 = r0 + 8;
#pragma unroll
        for (int ks = 0; ks < 4; ks++) {
            const int c0 = ks * 16 + tc * 2;
            qa_h[ks][0] = *(const uint32_t*)(Qh + r0 * HD + c0);
            qa_h[ks][1] = *(const uint32_t*)(Qh + r1 * HD + c0);
            qa_h[ks][2] = *(const uint32_t*)(Qh + r0 * HD + c0 + 8);
            qa_h[ks][3] = *(const uint32_t*)(Qh + r1 * HD + c0 + 8);
            qa_l[ks][0] = *(const uint32_t*)(Ql + r0 * HD + c0);
            qa_l[ks][1] = *(const uint32_t*)(Ql + r1 * HD + c0);
            qa_l[ks][2] = *(const uint32_t*)(Ql + r0 * HD + c0 + 8);
            qa_l[ks][3] = *(const uint32_t*)(Ql + r1 * HD + c0 + 8);
        }
    }

    float O[8][4];
#pragma unroll
    for (int i = 0; i < 8; i++)
#pragma unroll
        for (int j = 0; j < 4; j++) O[i][j] = 0.0f;
    float m0 = -1e30f, m1 = -1e30f, l0 = 0.0f, l1 = 0.0f;

    // coop-load assignments (K and V identical, token-major)
    const int r  = tid >> 1;
    const int hc = tid & 1;

    auto load_tile = [&](int kt, int s) {
        const uint32_t d = sb + s * AT_STG + r * 144 + hc * 64;
        const size_t src = ((size_t)head * Lq + kt + r) * HD + hc * 32;
#pragma unroll
        for (int c = 0; c < 4; c++) {
            CP16(d + AT_KH + c * 16, Kh + src + c * 8);
            CP16(d + AT_KL + c * 16, Kl + src + c * 8);
            CP16(d + AT_VH + c * 16, Vh + src + c * 8);
            CP16(d + AT_VL + c * 16, Vl + src + c * 8);
        }
    };

    // ldmatrix per-lane offsets
    const uint32_t kb_lo = (uint32_t)((lane & 7) * 144 + ((lane >> 3) & 1) * 16);
    const uint32_t vb_lo = (uint32_t)(((lane & 7) + ((lane >> 3) & 1) * 8) * 144);

    load_tile(0, 0); CP_COMMIT();

    for (int t = 0; t < 16; t++) {
        if (t + 1 < 16) { load_tile((t + 1) * 128, (t + 1) & 1); CP_COMMIT(); CP_WAIT(1); }
        else            { CP_WAIT(0); }
        __syncthreads();

        const uint32_t st = sb + (t & 1) * AT_STG;
        const uint32_t kh_base = st + AT_KH + kb_lo;
        const uint32_t vh_base = st + AT_VH + vb_lo;

        // S = Q K^T (16 ntiles of 8 tokens)
        float s[16][4];
#pragma unroll
        for (int nt = 0; nt < 16; nt++) {
            float c[4] = {0.f, 0.f, 0.f, 0.f};
#pragma unroll
            for (int ks = 0; ks < 4; ks++) {
                uint32_t bh[2], bl[2];
                ldsm_x2(bh, kh_base + nt * 8 * 144 + ks * 32);
                ldsm_x2(bl, kh_base + (AT_KL - AT_KH) + nt * 8 * 144 + ks * 32);
                mma_bf16(c, qa_h[ks], bh);
                mma_bf16(c, qa_h[ks], bl);
                mma_bf16(c, qa_l[ks], bh);
            }
            s[nt][0] = c[0]; s[nt][1] = c[1]; s[nt][2] = c[2]; s[nt][3] = c[3];
        }

        // online softmax (quad-reduced row max)
        float tm0 = -1e30f, tm1 = -1e30f;
#pragma unroll
        for (int nt = 0; nt < 16; nt++) {
            tm0 = fmaxf(tm0, fmaxf(s[nt][0], s[nt][1]));
            tm1 = fmaxf(tm1, fmaxf(s[nt][2], s[nt][3]));
        }
        tm0 = fmaxf(tm0, __shfl_xor_sync(0xffffffffu, tm0, 1));
        tm0 = fmaxf(tm0, __shfl_xor_sync(0xffffffffu, tm0, 2));
        tm1 = fmaxf(tm1, __shfl_xor_sync(0xffffffffu, tm1, 1));
        tm1 = fmaxf(tm1, __shfl_xor_sync(0xffffffffu, tm1, 2));

        const float nm0 = fmaxf(m0, tm0);
        const float nm1 = fmaxf(m1, tm1);
        const float cor0 = __expf(m0 - nm0);
        const float cor1 = __expf(m1 - nm1);
        m0 = nm0; m1 = nm1;
        l0 *= cor0; l1 *= cor1;
#pragma unroll
        for (int nt = 0; nt < 8; nt++) {
            O[nt][0] *= cor0; O[nt][1] *= cor0;
            O[nt][2] *= cor1; O[nt][3] *= cor1;
        }

        // exp + pack P fragments (C-frag layout == A-frag layout)
        uint32_t pah[8][4], pal[8][4];
#pragma unroll
        for (int ks = 0; ks < 8; ks++) {
            const float p0 = __expf(s[2 * ks][0] - m0);
            const float p1 = __expf(s[2 * ks][1] - m0);
            const float p2 = __expf(s[2 * ks][2] - m1);
            const float p3 = __expf(s[2 * ks][3] - m1);
            const float p4 = __expf(s[2 * ks + 1][0] - m0);
            const float p5 = __expf(s[2 * ks + 1][1] - m0);
            const float p6 = __expf(s[2 * ks + 1][2] - m1);
            const float p7 = __expf(s[2 * ks + 1][3] - m1);
            l0 += p0 + p1 + p4 + p5;
            l1 += p2 + p3 + p6 + p7;
            split_pack2(p0, p1, pah[ks][0], pal[ks][0]);
            split_pack2(p2, p3, pah[ks][1], pal[ks][1]);
            split_pack2(p4, p5, pah[ks][2], pal[ks][2]);
            split_pack2(p6, p7, pah[ks][3], pal[ks][3]);
        }

        // O += P V  (V token-major; B-frags via ldmatrix.x2.trans)
#pragma unroll
        for (int nt = 0; nt < 8; nt++) {
#pragma unroll
            for (int ks = 0; ks < 8; ks++) {
                uint32_t vh2[2], vl2[2];
                ldsm_x2t(vh2, vh_base + ks * 16 * 144 + nt * 16);
                ldsm_x2t(vl2, vh_base + (AT_VL - AT_VH) + ks * 16 * 144 + nt * 16);
                mma_bf16(O[nt], pah[ks], vh2);
                mma_bf16(O[nt], pah[ks], vl2);
                mma_bf16(O[nt], pal[ks], vh2);
            }
        }
        __syncthreads();
    }

    // finalize: quad-reduce l, normalize, write split-bf16 O
    l0 += __shfl_xor_sync(0xffffffffu, l0, 1);
    l0 += __shfl_xor_sync(0xffffffffu, l0, 2);
    l1 += __shfl_xor_sync(0xffffffffu, l1, 1);
    l1 += __shfl_xor_sync(0xffffffffu, l1, 2);
    const float inv0 = 1.0f / l0;
    const float inv1 = 1.0f / l1;

    const size_t r0 = (size_t)head * Lq + q0 + wid * 16 + g;
    const size_t r1 = r0 + 8;
#pragma unroll
    for (int nt = 0; nt < 8; nt++) {
        const int col = nt * 8 + tc * 2;
        uint32_t hi, lo;
        split_pack2(O[nt][0] * inv0, O[nt][1] * inv0, hi, lo);
        *(uint32_t*)&g_oh[r0 * HD + col] = hi;
        *(uint32_t*)&g_ol[r0 * HD + col] = lo;
        split_pack2(O[nt][2] * inv1, O[nt][3] * inv1, hi, lo);
        *(uint32_t*)&g_oh[r1 * HD + col] = hi;
        *(uint32_t*)&g_ol[r1 * HD + col] = lo;
    }
}

// ---------------------------------------------------------------------------
// Launch
// Inputs: 0=q, 1=k, 2=v, 3=in_proj_weight, 4=in_proj_bias, 5=out_w, 6=out_b
// ---------------------------------------------------------------------------
extern "C" void kernel_launch(void* const* d_in, const int* in_sizes, int n_in,
                              void* d_out, int out_size)
{
    const float* q  = (const float*)d_in[0];
    const float* k  = (const float*)d_in[1];
    const float* v  = (const float*)d_in[2];
    const float* w  = (const float*)d_in[3];
    const float* bi = (const float*)d_in[4];
    const float* ow = (const float*)d_in[5];
    const float* ob = (const float*)d_in[6];
    float* out = (float*)d_out;

    static bool configured = false;
    if (!configured) {
        cudaFuncSetAttribute(gemm_tc<0>, cudaFuncAttributeMaxDynamicSharedMemorySize, SMEM_T);
        cudaFuncSetAttribute(gemm_tc<1>, cudaFuncAttributeMaxDynamicSharedMemorySize, SMEM_T);
        cudaFuncSetAttribute(attn_mma,   cudaFuncAttributeMaxDynamicSharedMemorySize, SM_ATTN);
        configured = true;
    }

    prep_kernel<<<(unsigned)((NX4 + 255) / 256), 256>>>(q, k, v, w, ow);

    dim3 gp(Ee / 128, Mrows / 128, 3);
    gemm_tc<0><<<gp, 256, SMEM_T>>>(bi, nullptr);

    dim3 ga(Lq / 128, BHh);
    attn_mma<<<ga, 256, SM_ATTN>>>();

    dim3 go(Ee / 128, Mrows / 128);
    gemm_tc<1><<<go, 256, SMEM_T>>>(ob, out);
}

// round 12
// speedup vs baseline: 1.7814x; 1.7814x over previous
#include <cuda_runtime.h>
#include <cuda_bf16.h>
#include <cstdint>

// Problem constants
#define Lq   2048
#define Bb   4
#define Ee   1024
#define Hh   16
#define HD   64
#define BHh  64            // Bb*Hh
#define Mrows (Lq*Bb)      // 8192
#define SEG  ((size_t)BHh * Lq * HD)     // 8388608
#define ME   ((size_t)Mrows * Ee)        // 8388608
#define EE   ((size_t)Ee * Ee)           // 1048576

// bf16 split operands
__device__ __nv_bfloat16 g_xh[3 * ME], g_xl[3 * ME];       // q,k,v activations (prep)
__device__ __nv_bfloat16 g_wh[4 * EE], g_wl[4 * EE];       // in_proj_weight (3EE) + out_w (EE)
__device__ __nv_bfloat16 g_qkvh[3 * SEG], g_qkvl[3 * SEG]; // projected Q,K,V (BH,L,HD)
__device__ __nv_bfloat16 g_oh[SEG], g_ol[SEG];             // attention output

typedef unsigned long long u64;

// ---------------------------------------------------------------------------
// helpers
// ---------------------------------------------------------------------------
__device__ __forceinline__ uint32_t smem_u32(const void* p) {
    uint32_t a;
    asm("{ .reg .u64 t; cvta.to.shared.u64 t, %1; cvt.u32.u64 %0, t; }"
        : "=r"(a) : "l"(p));
    return a;
}
#define CP16(dst, src) asm volatile("cp.async.cg.shared.global [%0], [%1], 16;" :: "r"(dst), "l"(src))
#define CP_COMMIT()    asm volatile("cp.async.commit_group;" ::: "memory")
#define CP_WAIT(n)     asm volatile("cp.async.wait_group %0;" :: "n"(n) : "memory")

__device__ __forceinline__ void mma_bf16(float* c, const uint32_t* a, const uint32_t* b) {
    asm volatile(
        "mma.sync.aligned.m16n8k16.row.col.f32.bf16.bf16.f32 "
        "{%0,%1,%2,%3}, {%4,%5,%6,%7}, {%8,%9}, {%0,%1,%2,%3};"
        : "+f"(c[0]), "+f"(c[1]), "+f"(c[2]), "+f"(c[3])
        : "r"(a[0]), "r"(a[1]), "r"(a[2]), "r"(a[3]), "r"(b[0]), "r"(b[1]));
}

__device__ __forceinline__ void split_bf(float x, unsigned short& h, unsigned short& l) {
    h = __bfloat16_as_ushort(__float2bfloat16(x));
    float r = x - __bfloat162float(__ushort_as_bfloat16(h));
    l = __bfloat16_as_ushort(__float2bfloat16(r));
}
__device__ __forceinline__ void split_pack2(float f0, float f1, uint32_t& hi, uint32_t& lo) {
    unsigned short h0, h1, l0, l1;
    split_bf(f0, h0, l0); split_bf(f1, h1, l1);
    hi = (uint32_t)h0 | ((uint32_t)h1 << 16);
    lo = (uint32_t)l0 | ((uint32_t)l1 << 16);
}
__device__ __forceinline__ uint32_t get16(const uint4& v, int j) {
    uint32_t w = ((j >> 1) == 0) ? v.x : ((j >> 1) == 1) ? v.y : ((j >> 1) == 2) ? v.z : v.w;
    return (j & 1) ? (w >> 16) : (w & 0xffffu);
}

// ---------------------------------------------------------------------------
// prep: split activations + weights into bf16 hi/lo. One float4 per thread.
// ---------------------------------------------------------------------------
#define NX4 ((3 * ME + 4 * EE) / 4)
__global__ __launch_bounds__(256)
void prep_kernel(const float* __restrict__ q, const float* __restrict__ k,
                 const float* __restrict__ v, const float* __restrict__ w,
                 const float* __restrict__ ow)
{
    size_t i4 = (size_t)blockIdx.x * 256 + threadIdx.x;
    if (i4 >= NX4) return;
    size_t base = i4 * 4;
    const float* src;
    __nv_bfloat16 *dh, *dl;
    if (base < 3 * ME) {
        size_t z = base / ME, off = base - z * ME;
        src = (z == 0 ? q : z == 1 ? k : v) + off;
        dh = g_xh + base; dl = g_xl + base;
    } else {
        size_t off = base - 3 * ME;
        src = (off < 3 * EE) ? (w + off) : (ow + (off - 3 * EE));
        dh = g_wh + off; dl = g_wl + off;
    }
    float4 f = *(const float4*)src;
    uint32_t h0, l0, h1, l1;
    split_pack2(f.x, f.y, h0, l0);
    split_pack2(f.z, f.w, h1, l1);
    *(uint2*)dh = make_uint2(h0, h1);
    *(uint2*)dl = make_uint2(l0, l1);
}

// ---------------------------------------------------------------------------
// GEMM on mma.sync bf16x3 (scalar LDS frags). CTA 128x128, K-step 32,
// 2-stage cp.async, smem 80KB -> 2 CTAs/SM.
// MODE 0: QKV projection (writes bf16 hi/lo Q,K,V), MODE 1: out projection.
// ---------------------------------------------------------------------------
#define GROW  80                     // 32 bf16 = 64B data + 16B pad
#define TP    (128 * GROW)           // 10240
#define STG   (4 * TP)               // 40960
#define SMEM_T (2 * STG)             // 81920
#define NIT   32                     // 1024 / 32

template<int MODE>
__global__ __launch_bounds__(256, 2)
void gemm_tc(const float* __restrict__ bias, float* __restrict__ outp)
{
    extern __shared__ __align__(128) char smem[];
    const uint32_t sbase = smem_u32(smem);

    const int z   = (MODE == 0) ? blockIdx.z : 0;
    const int bm  = blockIdx.y * 128;
    const int bn  = blockIdx.x * 128;
    const int tid = threadIdx.x;
    const int wid  = tid >> 5;
    const int lane = tid & 31;
    const int wm = wid & 3;
    const int wn = wid >> 2;

    const int r    = tid >> 1;       // 0..127 tile row
    const int half = tid & 1;        // 16-element half of a 32-col row

    const __nv_bfloat16 *a_h, *a_l;
    if (MODE == 0) {
        size_t arow = (size_t)z * ME + (size_t)(bm + r) * Ee + half * 16;
        a_h = g_xh + arow; a_l = g_xl + arow;
    } else {
        const int mrow = bm + r;
        const int lA = mrow >> 2, bA = mrow & 3;
        size_t arow = ((size_t)bA * Hh * Lq + lA) * HD + half * 16;
        a_h = g_oh + arow; a_l = g_ol + arow;
    }
    const size_t brow = (size_t)((MODE == 0 ? z * Ee : 3 * Ee) + bn + r) * Ee + half * 16;
    const __nv_bfloat16* b_h = g_wh + brow;
    const __nv_bfloat16* b_l = g_wl + brow;

    const uint32_t dst_r = sbase + r * GROW + half * 32;

    float acc[2][8][4];
#pragma unroll
    for (int i = 0; i < 2; i++)
#pragma unroll
        for (int j = 0; j < 8; j++)
#pragma unroll
            for (int t = 0; t < 4; t++) acc[i][j][t] = 0.0f;

    auto load_stage = [&](int it, int s) {
        const uint32_t d = dst_r + s * STG;
        const size_t aoff = (MODE == 0)
            ? (size_t)it * 32
            : (size_t)(it >> 1) * ((size_t)Lq * HD) + (size_t)(it & 1) * 32;
        const size_t boff = (size_t)it * 32;
        const __nv_bfloat16* pa_h = a_h + aoff;
        const __nv_bfloat16* pa_l = a_l + aoff;
        const __nv_bfloat16* pb_h = b_h + boff;
        const __nv_bfloat16* pb_l = b_l + boff;
        CP16(d + 0 * TP,      pa_h); CP16(d + 0 * TP + 16, pa_h + 8);
        CP16(d + 1 * TP,      pa_l); CP16(d + 1 * TP + 16, pa_l + 8);
        CP16(d + 2 * TP,      pb_h); CP16(d + 2 * TP + 16, pb_h + 8);
        CP16(d + 3 * TP,      pb_l); CP16(d + 3 * TP + 16, pb_l + 8);
    };

    const int g  = lane >> 2;
    const int tc = lane & 3;

    load_stage(0, 0); CP_COMMIT();

    for (int it = 0; it < NIT; it++) {
        if (it + 1 < NIT) { load_stage(it + 1, (it + 1) & 1); CP_COMMIT(); CP_WAIT(1); }
        else              { CP_WAIT(0); }
        __syncthreads();

        const char* sa_h = smem + (it & 1) * STG + 0 * TP;
        const char* sa_l = smem + (it & 1) * STG + 1 * TP;
        const char* sb_h = smem + (it & 1) * STG + 2 * TP;
        const char* sb_l = smem + (it & 1) * STG + 3 * TP;

#pragma unroll
        for (int ks = 0; ks < 2; ks++) {
            const int cbyte = ks * 32 + tc * 4;
            uint32_t ah[2][4], al[2][4];
#pragma unroll
            for (int mt = 0; mt < 2; mt++) {
                const int r0 = wm * 32 + mt * 16 + g;
                const char* ph = sa_h + r0 * GROW + cbyte;
                const char* pl = sa_l + r0 * GROW + cbyte;
                ah[mt][0] = *(const uint32_t*)(ph);
                ah[mt][1] = *(const uint32_t*)(ph + 8 * GROW);
                ah[mt][2] = *(const uint32_t*)(ph + 16);
                ah[mt][3] = *(const uint32_t*)(ph + 8 * GROW + 16);
                al[mt][0] = *(const uint32_t*)(pl);
                al[mt][1] = *(const uint32_t*)(pl + 8 * GROW);
                al[mt][2] = *(const uint32_t*)(pl + 16);
                al[mt][3] = *(const uint32_t*)(pl + 8 * GROW + 16);
            }
#pragma unroll
            for (int nt = 0; nt < 8; nt++) {
                const int rn = wn * 64 + nt * 8 + g;
                const char* pbh = sb_h + rn * GROW + cbyte;
                const char* pbl = sb_l + rn * GROW + cbyte;
                uint32_t bh[2], bl[2];
                bh[0] = *(const uint32_t*)(pbh);
                bh[1] = *(const uint32_t*)(pbh + 16);
                bl[0] = *(const uint32_t*)(pbl);
                bl[1] = *(const uint32_t*)(pbl + 16);
#pragma unroll
                for (int mt = 0; mt < 2; mt++) {
                    mma_bf16(acc[mt][nt], ah[mt], bh);
                    mma_bf16(acc[mt][nt], ah[mt], bl);
                    mma_bf16(acc[mt][nt], al[mt], bh);
                }
            }
        }
        __syncthreads();
    }

    const float scale = (MODE == 0 && z == 0) ? 0.125f : 1.0f;
#pragma unroll
    for (int mt = 0; mt < 2; mt++) {
#pragma unroll
        for (int half_m = 0; half_m < 2; half_m++) {
            const int m = bm + wm * 32 + mt * 16 + g + half_m * 8;
#pragma unroll
            for (int nt = 0; nt < 8; nt++) {
                const int n = bn + wn * 64 + nt * 8 + tc * 2;
                const float c0 = acc[mt][nt][half_m * 2 + 0];
                const float c1 = acc[mt][nt][half_m * 2 + 1];
                if (MODE == 0) {
                    const int l = m >> 2, b = m & 3;
                    const int h = n >> 6, d = n & 63;
                    float v0 = scale * (c0 + bias[z * Ee + n]);
                    float v1 = scale * (c1 + bias[z * Ee + n + 1]);
                    uint32_t hi, lo;
                    split_pack2(v0, v1, hi, lo);
                    size_t addr = (size_t)z * SEG + ((size_t)(b * Hh + h) * Lq + l) * HD + d;
                    *(uint32_t*)&g_qkvh[addr] = hi;
                    *(uint32_t*)&g_qkvl[addr] = lo;
                } else {
                    float2 t;
                    t.x = c0 + bias[n];
                    t.y = c1 + bias[n + 1];
                    *(float2*)&outp[(size_t)m * Ee + n] = t;
                }
            }
        }
    }
}

// ---------------------------------------------------------------------------
// Flash attention on mma.sync bf16x3 (R10 structure), K-tile 64 tokens,
// smem 36KB single-buffer -> 2 CTAs/SM.
// K token-major (144B rows); V transposed hd-major (144B rows).
// ---------------------------------------------------------------------------
#define TKT    64
#define KROW   144                    // 64 hd * 2B + 16 pad
#define VTROW  144                    // 64 tok * 2B + 16 pad
#define SM_KH  0
#define SM_KL  (SM_KH + TKT * KROW)       // 9216
#define SM_VTH (SM_KL + TKT * KROW)       // 18432
#define SM_VTL (SM_VTH + 64 * VTROW)      // 27648
#define SM_ATTN (SM_VTL + 64 * VTROW)     // 36864

__global__ __launch_bounds__(256, 2)
void attn_mma()
{
    extern __shared__ __align__(128) char smem[];
    const uint32_t sb = smem_u32(smem);

    const int head = blockIdx.y;
    const int q0   = blockIdx.x * 128;
    const int tid  = threadIdx.x;
    const int wid  = tid >> 5;
    const int lane = tid & 31;
    const int g    = lane >> 2;
    const int tc   = lane & 3;

    const __nv_bfloat16* Qh = g_qkvh;
    const __nv_bfloat16* Ql = g_qkvl;
    const __nv_bfloat16* Kh = g_qkvh + SEG;
    const __nv_bfloat16* Kl = g_qkvl + SEG;
    const __nv_bfloat16* Vh = g_qkvh + 2 * SEG;
    const __nv_bfloat16* Vl = g_qkvl + 2 * SEG;

    // Q fragments in registers (per warp: 16 rows x 64 hd)
    uint32_t qa_h[4][4], qa_l[4][4];
    {
        const size_t r0 = (size_t)head * Lq + q0 + wid * 16 + g;
        const size_t r1 = r0 + 8;
#pragma unroll
        for (int ks = 0; ks < 4; ks++) {
            const int c0 = ks * 16 + tc * 2;
            qa_h[ks][0] = *(const uint32_t*)(Qh + r0 * HD + c0);
            qa_h[ks][1] = *(const uint32_t*)(Qh + r1 * HD + c0);
            qa_h[ks][2] = *(const uint32_t*)(Qh + r0 * HD + c0 + 8);
            qa_h[ks][3] = *(const uint32_t*)(Qh + r1 * HD + c0 + 8);
            qa_l[ks][0] = *(const uint32_t*)(Ql + r0 * HD + c0);
            qa_l[ks][1] = *(const uint32_t*)(Ql + r1 * HD + c0);
            qa_l[ks][2] = *(const uint32_t*)(Ql + r0 * HD + c0 + 8);
            qa_l[ks][3] = *(const uint32_t*)(Ql + r1 * HD + c0 + 8);
        }
    }

    float O[8][4];
#pragma unroll
    for (int i = 0; i < 8; i++)
#pragma unroll
        for (int j = 0; j < 4; j++) O[i][j] = 0.0f;
    float m0 = -1e30f, m1 = -1e30f, l0 = 0.0f, l1 = 0.0f;

    // coop-load assignments
    const int kr = tid >> 2;          // 0..63 K rows
    const int kq = tid & 3;           // 32B quarter
    const int vsp  = tid >> 7;        // V split (0=hi,1=lo)
    const int vidx = tid & 127;
    const int tb   = (vidx & 15) * 4; // token block (4 tokens)
    const int hb   = (vidx >> 4) * 8; // hd block (8 dims)
    const __nv_bfloat16* Vsrc = vsp ? Vl : Vh;
    const uint32_t vdst = sb + (vsp ? SM_VTL : SM_VTH);

    for (int kt = 0; kt < Lq; kt += TKT) {
        if (kt) __syncthreads();
        // K tile via cp.async (hi + lo)
        {
            const uint32_t dk = sb + kr * KROW + kq * 32;
            const size_t src = ((size_t)head * Lq + kt + kr) * HD + kq * 16;
            CP16(dk + SM_KH, Kh + src); CP16(dk + SM_KH + 16, Kh + src + 8);
            CP16(dk + SM_KL, Kl + src); CP16(dk + SM_KL + 16, Kl + src + 8);
            CP_COMMIT();
        }
        // V tile transposed (manual LDG + STS)
        {
            uint4 vv[4];
#pragma unroll
            for (int t = 0; t < 4; t++)
                vv[t] = *(const uint4*)(Vsrc + ((size_t)head * Lq + kt + tb + t) * HD + hb);
#pragma unroll
            for (int j = 0; j < 8; j++) {
#pragma unroll
                for (int tp = 0; tp < 2; tp++) {
                    uint32_t w0 = get16(vv[2 * tp], j);
                    uint32_t w1 = get16(vv[2 * tp + 1], j);
                    uint32_t pk = w0 | (w1 << 16);
                    const uint32_t a = vdst + (hb + j) * VTROW + (tb + 2 * tp) * 2;
                    asm volatile("st.shared.b32 [%0], %1;" :: "r"(a), "r"(pk) : "memory");
                }
            }
        }
        CP_WAIT(0);
        __syncthreads();

        // S = Q K^T (8 ntiles of 8 tokens)
        float s[8][4];
#pragma unroll
        for (int nt = 0; nt < 8; nt++) {
            float c[4] = {0.f, 0.f, 0.f, 0.f};
#pragma unroll
            for (int ks = 0; ks < 4; ks++) {
                const char* pb = smem + SM_KH + (nt * 8 + g) * KROW + ks * 32 + tc * 4;
                uint32_t bh[2], bl[2];
                bh[0] = *(const uint32_t*)(pb);
                bh[1] = *(const uint32_t*)(pb + 16);
                bl[0] = *(const uint32_t*)(pb + (SM_KL - SM_KH));
                bl[1] = *(const uint32_t*)(pb + (SM_KL - SM_KH) + 16);
                mma_bf16(c, qa_h[ks], bh);
                mma_bf16(c, qa_h[ks], bl);
                mma_bf16(c, qa_l[ks], bh);
            }
            s[nt][0] = c[0]; s[nt][1] = c[1]; s[nt][2] = c[2]; s[nt][3] = c[3];
        }

        // online softmax (quad-reduced row max)
        float tm0 = -1e30f, tm1 = -1e30f;
#pragma unroll
        for (int nt = 0; nt < 8; nt++) {
            tm0 = fmaxf(tm0, fmaxf(s[nt][0], s[nt][1]));
            tm1 = fmaxf(tm1, fmaxf(s[nt][2], s[nt][3]));
        }
        tm0 = fmaxf(tm0, __shfl_xor_sync(0xffffffffu, tm0, 1));
        tm0 = fmaxf(tm0, __shfl_xor_sync(0xffffffffu, tm0, 2));
        tm1 = fmaxf(tm1, __shfl_xor_sync(0xffffffffu, tm1, 1));
        tm1 = fmaxf(tm1, __shfl_xor_sync(0xffffffffu, tm1, 2));

        const float nm0 = fmaxf(m0, tm0);
        const float nm1 = fmaxf(m1, tm1);
        const float cor0 = __expf(m0 - nm0);
        const float cor1 = __expf(m1 - nm1);
        m0 = nm0; m1 = nm1;
        l0 *= cor0; l1 *= cor1;
#pragma unroll
        for (int nt = 0; nt < 8; nt++) {
            O[nt][0] *= cor0; O[nt][1] *= cor0;
            O[nt][2] *= cor1; O[nt][3] *= cor1;
        }

        // exp + pack P fragments (C-frag layout == A-frag layout)
        uint32_t pah[4][4], pal[4][4];
#pragma unroll
        for (int ks = 0; ks < 4; ks++) {
            const float p0 = __expf(s[2 * ks][0] - m0);
            const float p1 = __expf(s[2 * ks][1] - m0);
            const float p2 = __expf(s[2 * ks][2] - m1);
            const float p3 = __expf(s[2 * ks][3] - m1);
            const float p4 = __expf(s[2 * ks + 1][0] - m0);
            const float p5 = __expf(s[2 * ks + 1][1] - m0);
            const float p6 = __expf(s[2 * ks + 1][2] - m1);
            const float p7 = __expf(s[2 * ks + 1][3] - m1);
            l0 += p0 + p1 + p4 + p5;
            l1 += p2 + p3 + p6 + p7;
            split_pack2(p0, p1, pah[ks][0], pal[ks][0]);
            split_pack2(p2, p3, pah[ks][1], pal[ks][1]);
            split_pack2(p4, p5, pah[ks][2], pal[ks][2]);
            split_pack2(p6, p7, pah[ks][3], pal[ks][3]);
        }

        // O += P V (8 hd ntiles x 4 ksteps of 16 tokens)
#pragma unroll
        for (int nt = 0; nt < 8; nt++) {
#pragma unroll
            for (int ks = 0; ks < 4; ks++) {
                const char* pv = smem + SM_VTH + (nt * 8 + g) * VTROW + ks * 32 + tc * 4;
                uint32_t vh2[2], vl2[2];
                vh2[0] = *(const uint32_t*)(pv);
                vh2[1] = *(const uint32_t*)(pv + 16);
                vl2[0] = *(const uint32_t*)(pv + (SM_VTL - SM_VTH));
                vl2[1] = *(const uint32_t*)(pv + (SM_VTL - SM_VTH) + 16);
                mma_bf16(O[nt], pah[ks], vh2);
                mma_bf16(O[nt], pah[ks], vl2);
                mma_bf16(O[nt], pal[ks], vh2);
            }
        }
    }

    // finalize: quad-reduce l, normalize, write split-bf16 O
    l0 += __shfl_xor_sync(0xffffffffu, l0, 1);
    l0 += __shfl_xor_sync(0xffffffffu, l0, 2);
    l1 += __shfl_xor_sync(0xffffffffu, l1, 1);
    l1 += __shfl_xor_sync(0xffffffffu, l1, 2);
    const float inv0 = 1.0f / l0;
    const float inv1 = 1.0f / l1;

    const size_t r0 = (size_t)head * Lq + q0 + wid * 16 + g;
    const size_t r1 = r0 + 8;
#pragma unroll
    for (int nt = 0; nt < 8; nt++) {
        const int col = nt * 8 + tc * 2;
        uint32_t hi, lo;
        split_pack2(O[nt][0] * inv0, O[nt][1] * inv0, hi, lo);
        *(uint32_t*)&g_oh[r0 * HD + col] = hi;
        *(uint32_t*)&g_ol[r0 * HD + col] = lo;
        split_pack2(O[nt][2] * inv1, O[nt][3] * inv1, hi, lo);
        *(uint32_t*)&g_oh[r1 * HD + col] = hi;
        *(uint32_t*)&g_ol[r1 * HD + col] = lo;
    }
}

// ---------------------------------------------------------------------------
// Launch
// Inputs: 0=q, 1=k, 2=v, 3=in_proj_weight, 4=in_proj_bias, 5=out_w, 6=out_b
// ---------------------------------------------------------------------------
extern "C" void kernel_launch(void* const* d_in, const int* in_sizes, int n_in,
                              void* d_out, int out_size)
{
    const float* q  = (const float*)d_in[0];
    const float* k  = (const float*)d_in[1];
    const float* v  = (const float*)d_in[2];
    const float* w  = (const float*)d_in[3];
    const float* bi = (const float*)d_in[4];
    const float* ow = (const float*)d_in[5];
    const float* ob = (const float*)d_in[6];
    float* out = (float*)d_out;

    static bool configured = false;
    if (!configured) {
        cudaFuncSetAttribute(gemm_tc<0>, cudaFuncAttributeMaxDynamicSharedMemorySize, SMEM_T);
        cudaFuncSetAttribute(gemm_tc<1>, cudaFuncAttributeMaxDynamicSharedMemorySize, SMEM_T);
        cudaFuncSetAttribute(attn_mma,   cudaFuncAttributeMaxDynamicSharedMemorySize, SM_ATTN);
        configured = true;
    }

    prep_kernel<<<(unsigned)((NX4 + 255) / 256), 256>>>(q, k, v, w, ow);

    dim3 gp(Ee / 128, Mrows / 128, 3);
    gemm_tc<0><<<gp, 256, SMEM_T>>>(bi, nullptr);

    dim3 ga(Lq / 128, BHh);
    attn_mma<<<ga, 256, SM_ATTN>>>();

    dim3 go(Ee / 128, Mrows / 128);
    gemm_tc<1><<<go, 256, SMEM_T>>>(ob, out);
}

// round 13
// speedup vs baseline: 1.8426x; 1.0343x over previous
#include <cuda_runtime.h>
#include <cuda_bf16.h>
#include <cstdint>

// Problem constants
#define Lq   2048
#define Bb   4
#define Ee   1024
#define Hh   16
#define HD   64
#define BHh  64            // Bb*Hh
#define Mrows (Lq*Bb)      // 8192
#define SEG  ((size_t)BHh * Lq * HD)     // 8388608
#define ME   ((size_t)Mrows * Ee)        // 8388608
#define EE   ((size_t)Ee * Ee)           // 1048576

// bf16 split operands
__device__ __nv_bfloat16 g_xh[3 * ME], g_xl[3 * ME];       // q,k,v activations (prep)
__device__ __nv_bfloat16 g_wh[4 * EE], g_wl[4 * EE];       // in_proj_weight (3EE) + out_w (EE)
__device__ __nv_bfloat16 g_qkvh[3 * SEG], g_qkvl[3 * SEG]; // projected Q,K,V (BH,L,HD)
__device__ __nv_bfloat16 g_oh[SEG], g_ol[SEG];             // attention output

typedef unsigned long long u64;

// ---------------------------------------------------------------------------
// helpers
// ---------------------------------------------------------------------------
__device__ __forceinline__ uint32_t smem_u32(const void* p) {
    uint32_t a;
    asm("{ .reg .u64 t; cvta.to.shared.u64 t, %1; cvt.u32.u64 %0, t; }"
        : "=r"(a) : "l"(p));
    return a;
}
#define CP16(dst, src) asm volatile("cp.async.cg.shared.global [%0], [%1], 16;" :: "r"(dst), "l"(src))
#define CP_COMMIT()    asm volatile("cp.async.commit_group;" ::: "memory")
#define CP_WAIT(n)     asm volatile("cp.async.wait_group %0;" :: "n"(n) : "memory")

__device__ __forceinline__ void mma_bf16(float* c, const uint32_t* a, const uint32_t* b) {
    asm volatile(
        "mma.sync.aligned.m16n8k16.row.col.f32.bf16.bf16.f32 "
        "{%0,%1,%2,%3}, {%4,%5,%6,%7}, {%8,%9}, {%0,%1,%2,%3};"
        : "+f"(c[0]), "+f"(c[1]), "+f"(c[2]), "+f"(c[3])
        : "r"(a[0]), "r"(a[1]), "r"(a[2]), "r"(a[3]), "r"(b[0]), "r"(b[1]));
}

__device__ __forceinline__ void split_bf(float x, unsigned short& h, unsigned short& l) {
    h = __bfloat16_as_ushort(__float2bfloat16(x));
    float r = x - __bfloat162float(__ushort_as_bfloat16(h));
    l = __bfloat16_as_ushort(__float2bfloat16(r));
}
__device__ __forceinline__ void split_pack2(float f0, float f1, uint32_t& hi, uint32_t& lo) {
    unsigned short h0, h1, l0, l1;
    split_bf(f0, h0, l0); split_bf(f1, h1, l1);
    hi = (uint32_t)h0 | ((uint32_t)h1 << 16);
    lo = (uint32_t)l0 | ((uint32_t)l1 << 16);
}
__device__ __forceinline__ uint32_t get16(const uint4& v, int j) {
    uint32_t w = ((j >> 1) == 0) ? v.x : ((j >> 1) == 1) ? v.y : ((j >> 1) == 2) ? v.z : v.w;
    return (j & 1) ? (w >> 16) : (w & 0xffffu);
}

// ---------------------------------------------------------------------------
// prep: split activations + weights into bf16 hi/lo. One float4 per thread.
// ---------------------------------------------------------------------------
#define NX4 ((3 * ME + 4 * EE) / 4)
__global__ __launch_bounds__(256)
void prep_kernel(const float* __restrict__ q, const float* __restrict__ k,
                 const float* __restrict__ v, const float* __restrict__ w,
                 const float* __restrict__ ow)
{
    size_t i4 = (size_t)blockIdx.x * 256 + threadIdx.x;
    if (i4 >= NX4) return;
    size_t base = i4 * 4;
    const float* src;
    __nv_bfloat16 *dh, *dl;
    if (base < 3 * ME) {
        size_t z = base / ME, off = base - z * ME;
        src = (z == 0 ? q : z == 1 ? k : v) + off;
        dh = g_xh + base; dl = g_xl + base;
    } else {
        size_t off = base - 3 * ME;
        src = (off < 3 * EE) ? (w + off) : (ow + (off - 3 * EE));
        dh = g_wh + off; dl = g_wl + off;
    }
    float4 f = *(const float4*)src;
    uint32_t h0, l0, h1, l1;
    split_pack2(f.x, f.y, h0, l0);
    split_pack2(f.z, f.w, h1, l1);
    *(uint2*)dh = make_uint2(h0, h1);
    *(uint2*)dl = make_uint2(l0, l1);
}

// ---------------------------------------------------------------------------
// GEMM on mma.sync bf16x3 (scalar LDS frags). CTA 128x128, K-step 32,
// 2-stage cp.async, ONE barrier per K-step, smem 80KB -> 2 CTAs/SM.
// MODE 0: QKV projection (writes bf16 hi/lo Q,K,V), MODE 1: out projection.
// ---------------------------------------------------------------------------
#define GROW  80                     // 32 bf16 = 64B data + 16B pad
#define TP    (128 * GROW)           // 10240
#define STG   (4 * TP)               // 40960
#define SMEM_T (2 * STG)             // 81920
#define NIT   32                     // 1024 / 32

template<int MODE>
__global__ __launch_bounds__(256, 2)
void gemm_tc(const float* __restrict__ bias, float* __restrict__ outp)
{
    extern __shared__ __align__(128) char smem[];
    const uint32_t sbase = smem_u32(smem);

    const int z   = (MODE == 0) ? blockIdx.z : 0;
    const int bm  = blockIdx.y * 128;
    const int bn  = blockIdx.x * 128;
    const int tid = threadIdx.x;
    const int wid  = tid >> 5;
    const int lane = tid & 31;
    const int wm = wid & 3;
    const int wn = wid >> 2;

    const int r    = tid >> 1;       // 0..127 tile row
    const int half = tid & 1;        // 16-element half of a 32-col row

    const __nv_bfloat16 *a_h, *a_l;
    if (MODE == 0) {
        size_t arow = (size_t)z * ME + (size_t)(bm + r) * Ee + half * 16;
        a_h = g_xh + arow; a_l = g_xl + arow;
    } else {
        const int mrow = bm + r;
        const int lA = mrow >> 2, bA = mrow & 3;
        size_t arow = ((size_t)bA * Hh * Lq + lA) * HD + half * 16;
        a_h = g_oh + arow; a_l = g_ol + arow;
    }
    const size_t brow = (size_t)((MODE == 0 ? z * Ee : 3 * Ee) + bn + r) * Ee + half * 16;
    const __nv_bfloat16* b_h = g_wh + brow;
    const __nv_bfloat16* b_l = g_wl + brow;

    const uint32_t dst_r = sbase + r * GROW + half * 32;

    float acc[2][8][4];
#pragma unroll
    for (int i = 0; i < 2; i++)
#pragma unroll
        for (int j = 0; j < 8; j++)
#pragma unroll
            for (int t = 0; t < 4; t++) acc[i][j][t] = 0.0f;

    auto load_stage = [&](int it, int s) {
        const uint32_t d = dst_r + s * STG;
        const size_t aoff = (MODE == 0)
            ? (size_t)it * 32
            : (size_t)(it >> 1) * ((size_t)Lq * HD) + (size_t)(it & 1) * 32;
        const size_t boff = (size_t)it * 32;
        const __nv_bfloat16* pa_h = a_h + aoff;
        const __nv_bfloat16* pa_l = a_l + aoff;
        const __nv_bfloat16* pb_h = b_h + boff;
        const __nv_bfloat16* pb_l = b_l + boff;
        CP16(d + 0 * TP,      pa_h); CP16(d + 0 * TP + 16, pa_h + 8);
        CP16(d + 1 * TP,      pa_l); CP16(d + 1 * TP + 16, pa_l + 8);
        CP16(d + 2 * TP,      pb_h); CP16(d + 2 * TP + 16, pb_h + 8);
        CP16(d + 3 * TP,      pb_l); CP16(d + 3 * TP + 16, pb_l + 8);
    };

    const int g  = lane >> 2;
    const int tc = lane & 3;

    load_stage(0, 0); CP_COMMIT();

    for (int it = 0; it < NIT; it++) {
        CP_WAIT(0);
        __syncthreads();
        if (it + 1 < NIT) { load_stage(it + 1, (it + 1) & 1); CP_COMMIT(); }

        const char* sa_h = smem + (it & 1) * STG + 0 * TP;
        const char* sa_l = smem + (it & 1) * STG + 1 * TP;
        const char* sb_h = smem + (it & 1) * STG + 2 * TP;
        const char* sb_l = smem + (it & 1) * STG + 3 * TP;

#pragma unroll
        for (int ks = 0; ks < 2; ks++) {
            const int cbyte = ks * 32 + tc * 4;
            uint32_t ah[2][4], al[2][4];
#pragma unroll
            for (int mt = 0; mt < 2; mt++) {
                const int r0 = wm * 32 + mt * 16 + g;
                const char* ph = sa_h + r0 * GROW + cbyte;
                const char* pl = sa_l + r0 * GROW + cbyte;
                ah[mt][0] = *(const uint32_t*)(ph);
                ah[mt][1] = *(const uint32_t*)(ph + 8 * GROW);
                ah[mt][2] = *(const uint32_t*)(ph + 16);
                ah[mt][3] = *(const uint32_t*)(ph + 8 * GROW + 16);
                al[mt][0] = *(const uint32_t*)(pl);
                al[mt][1] = *(const uint32_t*)(pl + 8 * GROW);
                al[mt][2] = *(const uint32_t*)(pl + 16);
                al[mt][3] = *(const uint32_t*)(pl + 8 * GROW + 16);
            }
#pragma unroll
            for (int nt = 0; nt < 8; nt++) {
                const int rn = wn * 64 + nt * 8 + g;
                const char* pbh = sb_h + rn * GROW + cbyte;
                const char* pbl = sb_l + rn * GROW + cbyte;
                uint32_t bh[2], bl[2];
                bh[0] = *(const uint32_t*)(pbh);
                bh[1] = *(const uint32_t*)(pbh + 16);
                bl[0] = *(const uint32_t*)(pbl);
                bl[1] = *(const uint32_t*)(pbl + 16);
#pragma unroll
                for (int mt = 0; mt < 2; mt++) {
                    mma_bf16(acc[mt][nt], ah[mt], bh);
                    mma_bf16(acc[mt][nt], ah[mt], bl);
                    mma_bf16(acc[mt][nt], al[mt], bh);
                }
            }
        }
    }

    const float scale = (MODE == 0 && z == 0) ? 0.125f : 1.0f;
#pragma unroll
    for (int mt = 0; mt < 2; mt++) {
#pragma unroll
        for (int half_m = 0; half_m < 2; half_m++) {
            const int m = bm + wm * 32 + mt * 16 + g + half_m * 8;
#pragma unroll
            for (int nt = 0; nt < 8; nt++) {
                const int n = bn + wn * 64 + nt * 8 + tc * 2;
                const float c0 = acc[mt][nt][half_m * 2 + 0];
                const float c1 = acc[mt][nt][half_m * 2 + 1];
                if (MODE == 0) {
                    const int l = m >> 2, b = m & 3;
                    const int h = n >> 6, d = n & 63;
                    float v0 = scale * (c0 + bias[z * Ee + n]);
                    float v1 = scale * (c1 + bias[z * Ee + n + 1]);
                    uint32_t hi, lo;
                    split_pack2(v0, v1, hi, lo);
                    size_t addr = (size_t)z * SEG + ((size_t)(b * Hh + h) * Lq + l) * HD + d;
                    *(uint32_t*)&g_qkvh[addr] = hi;
                    *(uint32_t*)&g_qkvl[addr] = lo;
                } else {
                    float2 t;
                    t.x = c0 + bias[n];
                    t.y = c1 + bias[n + 1];
                    *(float2*)&outp[(size_t)m * Ee + n] = t;
                }
            }
        }
    }
}

// ---------------------------------------------------------------------------
// Flash attention on mma.sync bf16x3, K-tile 64 tokens, 2-stage pipeline
// (73.7KB smem -> 2 CTAs/SM). K token-major; V transposed hd-major.
// K prefetch via cp.async; V prefetch LDG issued after S-compute, STS after PV.
// ---------------------------------------------------------------------------
#define TKT    64
#define KROW   144
#define VTROW  144
#define SM_KH  0
#define SM_KL  (SM_KH + TKT * KROW)       // 9216
#define SM_VTH (SM_KL + TKT * KROW)       // 18432
#define SM_VTL (SM_VTH + 64 * VTROW)      // 27648
#define AT_STG (SM_VTL + 64 * VTROW)      // 36864 per stage
#define SM_ATTN (2 * AT_STG)              // 73728

__global__ __launch_bounds__(256, 2)
void attn_mma()
{
    extern __shared__ __align__(128) char smem[];
    const uint32_t sb = smem_u32(smem);

    const int head = blockIdx.y;
    const int q0   = blockIdx.x * 128;
    const int tid  = threadIdx.x;
    const int wid  = tid >> 5;
    const int lane = tid & 31;
    const int g    = lane >> 2;
    const int tc   = lane & 3;

    const __nv_bfloat16* Qh = g_qkvh;
    const __nv_bfloat16* Ql = g_qkvl;
    const __nv_bfloat16* Kh = g_qkvh + SEG;
    const __nv_bfloat16* Kl = g_qkvl + SEG;
    const __nv_bfloat16* Vh = g_qkvh + 2 * SEG;
    const __nv_bfloat16* Vl = g_qkvl + 2 * SEG;

    // Q fragments in registers (per warp: 16 rows x 64 hd)
    uint32_t qa_h[4][4], qa_l[4][4];
    {
        const size_t r0 = (size_t)head * Lq + q0 + wid * 16 + g;
        const size_t r1 = r0 + 8;
#pragma unroll
        for (int ks = 0; ks < 4; ks++) {
            const int c0 = ks * 16 + tc * 2;
            qa_h[ks][0] = *(const uint32_t*)(Qh + r0 * HD + c0);
            qa_h[ks][1] = *(const uint32_t*)(Qh + r1 * HD + c0);
            qa_h[ks][2] = *(const uint32_t*)(Qh + r0 * HD + c0 + 8);
            qa_h[ks][3] = *(const uint32_t*)(Qh + r1 * HD + c0 + 8);
            qa_l[ks][0] = *(const uint32_t*)(Ql + r0 * HD + c0);
            qa_l[ks][1] = *(const uint32_t*)(Ql + r1 * HD + c0);
            qa_l[ks][2] = *(const uint32_t*)(Ql + r0 * HD + c0 + 8);
            qa_l[ks][3] = *(const uint32_t*)(Ql + r1 * HD + c0 + 8);
        }
    }

    float O[8][4];
#pragma unroll
    for (int i = 0; i < 8; i++)
#pragma unroll
        for (int j = 0; j < 4; j++) O[i][j] = 0.0f;
    float m0 = -1e30f, m1 = -1e30f, l0 = 0.0f, l1 = 0.0f;

    // coop-load assignments
    const int kr = tid >> 2;          // 0..63 K rows
    const int kq = tid & 3;           // 32B quarter
    const int vsp  = tid >> 7;        // V split (0=hi,1=lo)
    const int vidx = tid & 127;
    const int tb   = (vidx & 15) * 4; // token block (4 tokens)
    const int hb   = (vidx >> 4) * 8; // hd block (8 dims)
    const __nv_bfloat16* Vsrc = vsp ? Vl : Vh;
    const uint32_t vbase = sb + (vsp ? SM_VTL : SM_VTH);

    auto load_k = [&](int kt, int s) {
        const uint32_t dk = sb + s * AT_STG + kr * KROW + kq * 32;
        const size_t src = ((size_t)head * Lq + kt + kr) * HD + kq * 16;
        CP16(dk + SM_KH, Kh + src); CP16(dk + SM_KH + 16, Kh + src + 8);
        CP16(dk + SM_KL, Kl + src); CP16(dk + SM_KL + 16, Kl + src + 8);
        CP_COMMIT();
    };
    auto load_v = [&](int kt, uint4* vv) {
#pragma unroll
        for (int t = 0; t < 4; t++)
            vv[t] = *(const uint4*)(Vsrc + ((size_t)head * Lq + kt + tb + t) * HD + hb);
    };
    auto store_v = [&](int s, const uint4* vv) {
        const uint32_t vdst = vbase + s * AT_STG;
#pragma unroll
        for (int j = 0; j < 8; j++) {
#pragma unroll
            for (int tp = 0; tp < 2; tp++) {
                uint32_t w0 = get16(vv[2 * tp], j);
                uint32_t w1 = get16(vv[2 * tp + 1], j);
                uint32_t pk = w0 | (w1 << 16);
                const uint32_t a = vdst + (hb + j) * VTROW + (tb + 2 * tp) * 2;
                asm volatile("st.shared.b32 [%0], %1;" :: "r"(a), "r"(pk) : "memory");
            }
        }
    };

    // prologue: tile 0 into stage 0
    {
        uint4 vv[4];
        load_k(0, 0);
        load_v(0, vv);
        store_v(0, vv);
    }

    for (int t = 0; t < 16 * (Lq / (16 * TKT)) * 1; t++) { /* placeholder avoided */ break; }

    const int NTILE = Lq / TKT;      // 32
    for (int t = 0; t < NTILE; t++) {
        CP_WAIT(0);
        __syncthreads();
        const int cur = t & 1;
        const int nxt = (t + 1) & 1;
        if (t + 1 < NTILE) load_k((t + 1) * TKT, nxt);

        const char* skh = smem + cur * AT_STG + SM_KH;

        // S = Q K^T (8 ntiles of 8 tokens)
        float s[8][4];
#pragma unroll
        for (int nt = 0; nt < 8; nt++) {
            float c[4] = {0.f, 0.f, 0.f, 0.f};
#pragma unroll
            for (int ks = 0; ks < 4; ks++) {
                const char* pb = skh + (nt * 8 + g) * KROW + ks * 32 + tc * 4;
                uint32_t bh[2], bl[2];
                bh[0] = *(const uint32_t*)(pb);
                bh[1] = *(const uint32_t*)(pb + 16);
                bl[0] = *(const uint32_t*)(pb + (SM_KL - SM_KH));
                bl[1] = *(const uint32_t*)(pb + (SM_KL - SM_KH) + 16);
                mma_bf16(c, qa_h[ks], bh);
                mma_bf16(c, qa_h[ks], bl);
                mma_bf16(c, qa_l[ks], bh);
            }
            s[nt][0] = c[0]; s[nt][1] = c[1]; s[nt][2] = c[2]; s[nt][3] = c[3];
        }

        // prefetch V of next tile into registers (latency hides under softmax+PV)
        uint4 vv[4];
        if (t + 1 < NTILE) load_v((t + 1) * TKT, vv);

        // online softmax (quad-reduced row max)
        float tm0 = -1e30f, tm1 = -1e30f;
#pragma unroll
        for (int nt = 0; nt < 8; nt++) {
            tm0 = fmaxf(tm0, fmaxf(s[nt][0], s[nt][1]));
            tm1 = fmaxf(tm1, fmaxf(s[nt][2], s[nt][3]));
        }
        tm0 = fmaxf(tm0, __shfl_xor_sync(0xffffffffu, tm0, 1));
        tm0 = fmaxf(tm0, __shfl_xor_sync(0xffffffffu, tm0, 2));
        tm1 = fmaxf(tm1, __shfl_xor_sync(0xffffffffu, tm1, 1));
        tm1 = fmaxf(tm1, __shfl_xor_sync(0xffffffffu, tm1, 2));

        const float nm0 = fmaxf(m0, tm0);
        const float nm1 = fmaxf(m1, tm1);
        const float cor0 = __expf(m0 - nm0);
        const float cor1 = __expf(m1 - nm1);
        m0 = nm0; m1 = nm1;
        l0 *= cor0; l1 *= cor1;
#pragma unroll
        for (int nt = 0; nt < 8; nt++) {
            O[nt][0] *= cor0; O[nt][1] *= cor0;
            O[nt][2] *= cor1; O[nt][3] *= cor1;
        }

        // exp + pack P fragments (C-frag layout == A-frag layout)
        uint32_t pah[4][4], pal[4][4];
#pragma unroll
        for (int ks = 0; ks < 4; ks++) {
            const float p0 = __expf(s[2 * ks][0] - m0);
            const float p1 = __expf(s[2 * ks][1] - m0);
            const float p2 = __expf(s[2 * ks][2] - m1);
            const float p3 = __expf(s[2 * ks][3] - m1);
            const float p4 = __expf(s[2 * ks + 1][0] - m0);
            const float p5 = __expf(s[2 * ks + 1][1] - m0);
            const float p6 = __expf(s[2 * ks + 1][2] - m1);
            const float p7 = __expf(s[2 * ks + 1][3] - m1);
            l0 += p0 + p1 + p4 + p5;
            l1 += p2 + p3 + p6 + p7;
            split_pack2(p0, p1, pah[ks][0], pal[ks][0]);
            split_pack2(p2, p3, pah[ks][1], pal[ks][1]);
            split_pack2(p4, p5, pah[ks][2], pal[ks][2]);
            split_pack2(p6, p7, pah[ks][3], pal[ks][3]);
        }

        // O += P V (8 hd ntiles x 4 ksteps of 16 tokens)
        const char* svh = smem + cur * AT_STG + SM_VTH;
#pragma unroll
        for (int nt = 0; nt < 8; nt++) {
#pragma unroll
            for (int ks = 0; ks < 4; ks++) {
                const char* pv = svh + (nt * 8 + g) * VTROW + ks * 32 + tc * 4;
                uint32_t vh2[2], vl2[2];
                vh2[0] = *(const uint32_t*)(pv);
                vh2[1] = *(const uint32_t*)(pv + 16);
                vl2[0] = *(const uint32_t*)(pv + (SM_VTL - SM_VTH));
                vl2[1] = *(const uint32_t*)(pv + (SM_VTL - SM_VTH) + 16);
                mma_bf16(O[nt], pah[ks], vh2);
                mma_bf16(O[nt], pah[ks], vl2);
                mma_bf16(O[nt], pal[ks], vh2);
            }
        }

        // scatter prefetched V into next stage (visible after next barrier)
        if (t + 1 < NTILE) store_v(nxt, vv);
    }

    // finalize: quad-reduce l, normalize, write split-bf16 O
    l0 += __shfl_xor_sync(0xffffffffu, l0, 1);
    l0 += __shfl_xor_sync(0xffffffffu, l0, 2);
    l1 += __shfl_xor_sync(0xffffffffu, l1, 1);
    l1 += __shfl_xor_sync(0xffffffffu, l1, 2);
    const float inv0 = 1.0f / l0;
    const float inv1 = 1.0f / l1;

    const size_t r0 = (size_t)head * Lq + q0 + wid * 16 + g;
    const size_t r1 = r0 + 8;
#pragma unroll
    for (int nt = 0; nt < 8; nt++) {
        const int col = nt * 8 + tc * 2;
        uint32_t hi, lo;
        split_pack2(O[nt][0] * inv0, O[nt][1] * inv0, hi, lo);
        *(uint32_t*)&g_oh[r0 * HD + col] = hi;
        *(uint32_t*)&g_ol[r0 * HD + col] = lo;
        split_pack2(O[nt][2] * inv1, O[nt][3] * inv1, hi, lo);
        *(uint32_t*)&g_oh[r1 * HD + col] = hi;
        *(uint32_t*)&g_ol[r1 * HD + col] = lo;
    }
}

// ---------------------------------------------------------------------------
// Launch
// Inputs: 0=q, 1=k, 2=v, 3=in_proj_weight, 4=in_proj_bias, 5=out_w, 6=out_b
// ---------------------------------------------------------------------------
extern "C" void kernel_launch(void* const* d_in, const int* in_sizes, int n_in,
                              void* d_out, int out_size)
{
    const float* q  = (const float*)d_in[0];
    const float* k  = (const float*)d_in[1];
    const float* v  = (const float*)d_in[2];
    const float* w  = (const float*)d_in[3];
    const float* bi = (const float*)d_in[4];
    const float* ow = (const float*)d_in[5];
    const float* ob = (const float*)d_in[6];
    float* out = (float*)d_out;

    static bool configured = false;
    if (!configured) {
        cudaFuncSetAttribute(gemm_tc<0>, cudaFuncAttributeMaxDynamicSharedMemorySize, SMEM_T);
        cudaFuncSetAttribute(gemm_tc<1>, cudaFuncAttributeMaxDynamicSharedMemorySize, SMEM_T);
        cudaFuncSetAttribute(attn_mma,   cudaFuncAttributeMaxDynamicSharedMemorySize, SM_ATTN);
        configured = true;
    }

    prep_kernel<<<(unsigned)((NX4 + 255) / 256), 256>>>(q, k, v, w, ow);

    dim3 gp(Ee / 128, Mrows / 128, 3);
    gemm_tc<0><<<gp, 256, SMEM_T>>>(bi, nullptr);

    dim3 ga(Lq / 128, BHh);
    attn_mma<<<ga, 256, SM_ATTN>>>();

    dim3 go(Ee / 128, Mrows / 128);
    gemm_tc<1><<<go, 256, SMEM_T>>>(ob, out);
}